// round 16
// baseline (speedup 1.0000x reference)
#include <cuda_runtime.h>
#include <cstdint>

#define BB 8
#define SS 2048
#define DD 768
#define HH 12
#define LISTN 8

typedef unsigned long long ull;

// scratch (allocation-free rule: __device__ globals)
__device__ float g_q[BB * SS * HH];
__device__ float g_k[BB * SS * HH];
__device__ float g_v[BB * SS * HH];

// ---------- f32x2 helpers ----------
static __device__ __forceinline__ ull pk2(float a, float b) {
    ull r;
    asm("mov.b64 %0, {%1, %2};"
        : "=l"(r) : "r"(__float_as_uint(a)), "r"(__float_as_uint(b)));
    return r;
}
static __device__ __forceinline__ void upk2(ull v, float& a, float& b) {
    unsigned int x, y;
    asm("mov.b64 {%0, %1}, %2;" : "=r"(x), "=r"(y) : "l"(v));
    a = __uint_as_float(x);
    b = __uint_as_float(y);
}
static __device__ __forceinline__ void fma2(ull& d, ull a, ull b) {
    asm("fma.rn.f32x2 %0, %1, %2, %0;" : "+l"(d) : "l"(a), "l"(b));
}
static __device__ __forceinline__ ull add2(ull a, ull b) {
    ull r;
    asm("add.rn.f32x2 %0, %1, %2;" : "=l"(r) : "l"(a), "l"(b));
    return r;
}

// ---------- cp.async helpers ----------
static __device__ __forceinline__ void cpa16(void* smem, const void* g) {
    unsigned int sa = (unsigned int)__cvta_generic_to_shared(smem);
    asm volatile("cp.async.cg.shared.global [%0], [%1], 16;" :: "r"(sa), "l"(g));
}
static __device__ __forceinline__ void cpa_commit() {
    asm volatile("cp.async.commit_group;");
}
static __device__ __forceinline__ void cpa_wait1() {
    asm volatile("cp.async.wait_group 1;");
}
static __device__ __forceinline__ void cpa_wait0() {
    asm volatile("cp.async.wait_group 0;");
}

// =====================================================================
// Kernel 1: fused QKV projection — R14 ring math at 128 threads x 512
// blocks (32 rows; rp = tid>>3 owns rows 2rp,2rp+1; sub = tid&7 splits
// D 8-way). 3-stage cp.async ring, ONE barrier per chunk. 54KB smem ->
// 4 blocks/SM; barriers span only 4 warps.
// =====================================================================
#define XS_F (32 * 68)          // floats per x buffer
#define WS_F (64 * 36)          // floats per W buffer
#define PROJ_SMEM ((3 * (XS_F + WS_F)) * 4)   // 53760 B

__global__ __launch_bounds__(128) void proj_kernel(
    const float* __restrict__ x,
    const float* __restrict__ wq,
    const float* __restrict__ wk,
    const float* __restrict__ wv)
{
    extern __shared__ __align__(16) float psm[];
    float* xs = psm;                 // [3][32*68]
    float* ws = psm + 3 * XS_F;      // [3][64*36]

    const int tid = threadIdx.x;
    const int sub = tid & 7;
    const int rp  = tid >> 3;
    const size_t rowBase = (size_t)blockIdx.x * 32;

    const float* warr[3] = { wq, wk, wv };

    auto stage = [&](int s, int dc) {
        float* xb = xs + s * XS_F;
        float* wb = ws + s * WS_F;
#pragma unroll
        for (int i = tid; i < 512; i += 128) {
            int row = i >> 4, col = i & 15;
            cpa16(&xb[row * 68 + col * 4],
                  x + (rowBase + row) * DD + dc + col * 4);
        }
        for (int i = tid; i < 576; i += 128) {
            int a = i / 192, rem = i - a * 192;
            int c = rem / 3,  j = rem - c * 3;
            cpa16(&wb[c * 36 + a * 12 + j * 4],
                  warr[a] + (size_t)dc * HH + rem * 4);
        }
        cpa_commit();
    };

    ull accA[18], accB[18];
#pragma unroll
    for (int i = 0; i < 18; i++) { accA[i] = 0ULL; accB[i] = 0ULL; }

    stage(0, 0);
    stage(1, 64);

    for (int ch = 0; ch < 12; ch++) {
        if (ch < 11) cpa_wait1();
        else         cpa_wait0();
        __syncthreads();             // chunk ch visible; everyone done ch-1
        if (ch < 10) stage((ch + 2) % 3, (ch + 2) * 64);

        const float* xb = xs + (ch % 3) * XS_F;
        const float* wb = ws + (ch % 3) * WS_F;
        const float* xrA = xb + (2 * rp) * 68;
        const float* xrB = xrA + 68;
#pragma unroll
        for (int ci = 0; ci < 8; ci++) {
            int c = ci * 8 + sub;
            ull xA = pk2(xrA[c], xrA[c]);
            ull xB = pk2(xrB[c], xrB[c]);
            const ulonglong2* wrow = (const ulonglong2*)(wb + c * 36);
#pragma unroll
            for (int j = 0; j < 9; j++) {
                ulonglong2 u = wrow[j];
                fma2(accA[2 * j],     xA, u.x);
                fma2(accA[2 * j + 1], xA, u.y);
                fma2(accB[2 * j],     xB, u.x);
                fma2(accB[2 * j + 1], xB, u.y);
            }
        }
    }

    // combine the 8 d-split partials (lanes sub 0..7 adjacent)
#pragma unroll
    for (int off = 1; off < 8; off <<= 1) {
#pragma unroll
        for (int j = 0; j < 18; j++) {
            accA[j] = add2(accA[j], __shfl_xor_sync(0xffffffffu, accA[j], off));
            accB[j] = add2(accB[j], __shfl_xor_sync(0xffffffffu, accB[j], off));
        }
    }

    if (sub == 0) {
#pragma unroll
        for (int half = 0; half < 2; half++) {
            ull* acc = half ? accB : accA;
            float o[36];
#pragma unroll
            for (int j = 0; j < 18; j++) upk2(acc[j], o[2 * j], o[2 * j + 1]);
            const size_t row = rowBase + 2 * rp + half;
            float4* qo = (float4*)&g_q[row * HH];
            float4* ko = (float4*)&g_k[row * HH];
            float4* vo = (float4*)&g_v[row * HH];
            qo[0] = make_float4(o[0],  o[1],  o[2],  o[3]);
            qo[1] = make_float4(o[4],  o[5],  o[6],  o[7]);
            qo[2] = make_float4(o[8],  o[9],  o[10], o[11]);
            ko[0] = make_float4(o[12], o[13], o[14], o[15]);
            ko[1] = make_float4(o[16], o[17], o[18], o[19]);
            ko[2] = make_float4(o[20], o[21], o[22], o[23]);
            vo[0] = make_float4(o[24], o[25], o[26], o[27]);
            vo[1] = make_float4(o[28], o[29], o[30], o[31]);
            vo[2] = make_float4(o[32], o[33], o[34], o[35]);
        }
    }
}

// =====================================================================
// Kernel 2: attention, KEY-PAIR packing. 512 blocks = (b, 32-row tile),
// 256 threads: grp = tid>>4 owns rows 2grp,2grp+1; sub = tid&15 owns
// key-pairs p == sub (mod 16). ALL 2048 keys staged ONCE (one barrier)
// as 6 h-pair planes of (k_{2p}h, k_{2p+1}h) ulonglong2 -> 48B/key.
// q duplicated (q_h,q_h) per row. Per it: 2 rows x 2 keys via 6
// LDS.128 + 24 FFMA2 + ONE combined rare branch. Trackers/lists/
// gather/fallback identical to the proven scheme.
// =====================================================================
static __device__ __forceinline__ ull packSI(float s, int i) {
    return ((ull)__float_as_uint(s) << 32) | (unsigned int)i;
}

__global__ __launch_bounds__(256, 2) void attn_kernel(
    const int* __restrict__ mask,
    float* __restrict__ outp)
{
    extern __shared__ __align__(16) char smem_raw[];
    ulonglong2* ks = (ulonglong2*)smem_raw;              // [6][1024] = 98304 B
    ull*  slist = (ull*)(smem_raw + 98304);              // 32*8*8 = 2048
    int*  scnt  = (int*)(smem_raw + 98304 + 2048);       // 128
    int*  sflag = (int*)(smem_raw + 98304 + 2048 + 128); // 128

    const int tid  = threadIdx.x;
    const int b    = blockIdx.x >> 6;
    const int tile = blockIdx.x & 63;
    const int sub  = tid & 15;
    const int grp  = tid >> 4;

    const float* kbase = g_k + (size_t)b * SS * HH;
    const float* vbase = g_v + (size_t)b * SS * HH;
    const int*   mb    = mask + b * SS;

    const float sc = 0.28867513459481287f;   // 1/sqrt(12)
    const size_t rowG0 = (size_t)b * SS + tile * 32 + grp * 2;

    if (tid < 32) { scnt[tid] = 0; sflag[tid] = 0; }

    // q for 2 rows, scale folded, duplicated (q_h,q_h)
    ull qd0[12], qd1[12];
    {
        const float4* qp = (const float4*)(g_q + rowG0 * HH);
        float4 a0 = qp[0], a1 = qp[1], a2 = qp[2];
        float4 b0 = qp[3], b1 = qp[4], b2 = qp[5];
        float f0[12] = { a0.x,a0.y,a0.z,a0.w, a1.x,a1.y,a1.z,a1.w,
                         a2.x,a2.y,a2.z,a2.w };
        float f1[12] = { b0.x,b0.y,b0.z,b0.w, b1.x,b1.y,b1.z,b1.w,
                         b2.x,b2.y,b2.z,b2.w };
#pragma unroll
        for (int h = 0; h < 12; h++) {
            qd0[h] = pk2(f0[h] * sc, f0[h] * sc);
            qd1[h] = pk2(f1[h] * sc, f1[h] * sc);
        }
    }

    // ---- stage ALL 2048 keys as key-pair planes; masked keys zeroed ----
    for (int p = tid; p < 1024; p += 256) {
        const float4* ka4 = (const float4*)(kbase + (size_t)(2 * p) * HH);
        float4 x0 = ka4[0], x1 = ka4[1], x2 = ka4[2];
        float4 y0 = ka4[3], y1 = ka4[4], y2 = ka4[5];
        if (!mb[2 * p])     { x0 = make_float4(0,0,0,0); x1 = x0; x2 = x0; }
        if (!mb[2 * p + 1]) { y0 = make_float4(0,0,0,0); y1 = y0; y2 = y0; }
        float ka[12] = { x0.x,x0.y,x0.z,x0.w, x1.x,x1.y,x1.z,x1.w,
                         x2.x,x2.y,x2.z,x2.w };
        float kb[12] = { y0.x,y0.y,y0.z,y0.w, y1.x,y1.y,y1.z,y1.w,
                         y2.x,y2.y,y2.z,y2.w };
#pragma unroll
        for (int j = 0; j < 6; j++) {
            ulonglong2 u;
            u.x = pk2(ka[2 * j],     kb[2 * j]);
            u.y = pk2(ka[2 * j + 1], kb[2 * j + 1]);
            ks[j * 1024 + p] = u;
        }
    }
    __syncthreads();

    const float NINF = __int_as_float(0xff800000);
    float t1a = NINF, t2a = NINF, t3a = NINF, tha = 0.f;
    float t1b = NINF, t2b = NINF, t3b = NINF, thb = 0.f;
    int   j1a = 0, j2a = 0, j1b = 0, j2b = 0;

    // ---------- pass 1: 64 iterations over this thread's key-pairs ----------
    const ulonglong2* kp = ks + sub;
    for (int it = 0; it < 64; it++, kp += 16) {
        ull a0 = 0ULL, a1 = 0ULL;
#pragma unroll
        for (int j = 0; j < 6; j++) {
            ulonglong2 u = kp[j * 1024];
            fma2(a0, qd0[2 * j],     u.x);
            fma2(a0, qd0[2 * j + 1], u.y);
            fma2(a1, qd1[2 * j],     u.x);
            fma2(a1, qd1[2 * j + 1], u.y);
        }
        float s0, s1, s2, s3;
        upk2(a0, s0, s1);           // row0: keys 2p, 2p+1
        upk2(a1, s2, s3);           // row1: keys 2p, 2p+1

        if (fmaxf(fmaxf(s0, s1) - tha, fmaxf(s2, s3) - thb) > 0.f) {  // rare
            int k0 = ((it << 4) + sub) * 2;
#pragma unroll
            for (int e = 0; e < 2; e++) {
                float s = e ? s1 : s0;
                int   k = k0 + e;
                if (s > tha) {
                    if (s > t1a) {
                        t3a = t2a; t2a = t1a; j2a = j1a;
                        t1a = s;   j1a = k;
                        tha = fmaxf(s - 30.f, 0.f);
                    } else if (s > t2a) { t3a = t2a; t2a = s; j2a = k; }
                    else t3a = fmaxf(t3a, s);
                }
            }
#pragma unroll
            for (int e = 0; e < 2; e++) {
                float s = e ? s3 : s2;
                int   k = k0 + e;
                if (s > thb) {
                    if (s > t1b) {
                        t3b = t2b; t2b = t1b; j2b = j1b;
                        t1b = s;   j1b = k;
                        thb = fmaxf(s - 30.f, 0.f);
                    } else if (s > t2b) { t3b = t2b; t2b = s; j2b = k; }
                    else t3b = fmaxf(t3b, s);
                }
            }
        }
    }

    // row maxes across the 16 sub-threads (xor<16 stays in half-warp)
    float ma = t1a, mbx = t1b;
#pragma unroll
    for (int off = 1; off < 16; off <<= 1) {
        ma  = fmaxf(ma,  __shfl_xor_sync(0xffffffffu, ma,  off));
        mbx = fmaxf(mbx, __shfl_xor_sync(0xffffffffu, mbx, off));
    }

    // publish candidates to per-row lists
    {
        int row0 = grp * 2, row1 = row0 + 1;
        float thr0 = ma - 30.f, thr1 = mbx - 30.f;
        if (t1a > thr0) {
            int slot = atomicAdd(&scnt[row0], 1);
            if (slot < LISTN) slist[row0 * LISTN + slot] = packSI(t1a, j1a);
        }
        if (t2a > thr0) {
            int slot = atomicAdd(&scnt[row0], 1);
            if (slot < LISTN) slist[row0 * LISTN + slot] = packSI(t2a, j2a);
        }
        if (t3a > thr0) sflag[row0] = 1;
        if (t1b > thr1) {
            int slot = atomicAdd(&scnt[row1], 1);
            if (slot < LISTN) slist[row1 * LISTN + slot] = packSI(t1b, j1b);
        }
        if (t2b > thr1) {
            int slot = atomicAdd(&scnt[row1], 1);
            if (slot < LISTN) slist[row1 * LISTN + slot] = packSI(t2b, j2b);
        }
        if (t3b > thr1) sflag[row1] = 1;
    }
    __syncthreads();

    // ---------- pass 2: gather (sub==0 threads handle their 2 rows) ----------
    if (sub == 0) {
        float mrow2[2] = { ma, mbx };
#pragma unroll
        for (int r = 0; r < 2; r++) {
            int row = grp * 2 + r;
            float den = 0.f;
            float o[12];
#pragma unroll
            for (int h = 0; h < 12; h++) o[h] = 0.f;

            float qs[12];
            {
                const float4* qp = (const float4*)(g_q + (rowG0 + r) * HH);
                float4 a = qp[0], c = qp[1], e = qp[2];
                qs[0] = a.x*sc;  qs[1] = a.y*sc;  qs[2] = a.z*sc;  qs[3] = a.w*sc;
                qs[4] = c.x*sc;  qs[5] = c.y*sc;  qs[6] = c.z*sc;  qs[7] = c.w*sc;
                qs[8] = e.x*sc;  qs[9] = e.y*sc;  qs[10]= e.z*sc;  qs[11]= e.w*sc;
            }

            int n = scnt[row];
            if (n > 0 && n <= LISTN && !sflag[row]) {
                float m = mrow2[r];
                for (int e = 0; e < n; e++) {
                    ull v = slist[row * LISTN + e];
                    float s = __uint_as_float((unsigned int)(v >> 32));
                    int idx = (int)(v & 0xffffffffu);
                    float pe = __expf(s - m);
                    den += pe;
                    const float4* vr = (const float4*)(vbase + (size_t)idx * HH);
                    float4 v0 = vr[0], v1 = vr[1], v2 = vr[2];
                    o[0] += pe * v0.x;  o[1] += pe * v0.y;  o[2] += pe * v0.z;  o[3] += pe * v0.w;
                    o[4] += pe * v1.x;  o[5] += pe * v1.y;  o[6] += pe * v1.z;  o[7] += pe * v1.w;
                    o[8] += pe * v2.x;  o[9] += pe * v2.y;  o[10]+= pe * v2.z;  o[11]+= pe * v2.w;
                }
            } else {
                // exact fallback: two fp32 sweeps over the whole row,
                // recomputing the true row max (independent of pass-1 state)
                float m = NINF;
                for (int ti = 0; ti < SS; ti++) {
                    if (mb[ti]) {
                        const float4* kr = (const float4*)(kbase + (size_t)ti * HH);
                        float4 k0 = kr[0], k1 = kr[1], k2 = kr[2];
                        float s = qs[0]*k0.x + qs[1]*k0.y + qs[2]*k0.z + qs[3]*k0.w
                                + qs[4]*k1.x + qs[5]*k1.y + qs[6]*k1.z + qs[7]*k1.w
                                + qs[8]*k2.x + qs[9]*k2.y + qs[10]*k2.z + qs[11]*k2.w;
                        m = fmaxf(m, s);
                    }
                }
                for (int ti = 0; ti < SS; ti++) {
                    if (mb[ti]) {
                        const float4* kr = (const float4*)(kbase + (size_t)ti * HH);
                        float4 k0 = kr[0], k1 = kr[1], k2 = kr[2];
                        float s = qs[0]*k0.x + qs[1]*k0.y + qs[2]*k0.z + qs[3]*k0.w
                                + qs[4]*k1.x + qs[5]*k1.y + qs[6]*k1.z + qs[7]*k1.w
                                + qs[8]*k2.x + qs[9]*k2.y + qs[10]*k2.z + qs[11]*k2.w;
                        if (s > m - 40.f) {
                            float pe = __expf(s - m);
                            den += pe;
                            const float4* vr = (const float4*)(vbase + (size_t)ti * HH);
                            float4 v0 = vr[0], v1 = vr[1], v2 = vr[2];
                            o[0] += pe * v0.x;  o[1] += pe * v0.y;  o[2] += pe * v0.z;  o[3] += pe * v0.w;
                            o[4] += pe * v1.x;  o[5] += pe * v1.y;  o[6] += pe * v1.z;  o[7] += pe * v1.w;
                            o[8] += pe * v2.x;  o[9] += pe * v2.y;  o[10]+= pe * v2.z;  o[11]+= pe * v2.w;
                        }
                    }
                }
            }

            float inv = 1.f / den;
            float4* op = (float4*)(outp + (rowG0 + r) * HH);
            op[0] = make_float4(o[0]*inv, o[1]*inv, o[2]*inv,  o[3]*inv);
            op[1] = make_float4(o[4]*inv, o[5]*inv, o[6]*inv,  o[7]*inv);
            op[2] = make_float4(o[8]*inv, o[9]*inv, o[10]*inv, o[11]*inv);
        }
    }
}

// =====================================================================
// launch
// =====================================================================
extern "C" void kernel_launch(void* const* d_in, const int* in_sizes, int n_in,
                              void* d_out, int out_size) {
    const float* x    = (const float*)d_in[0];
    const int*   mask = (const int*)d_in[1];
    const float* wk   = (const float*)d_in[2];   // key_weight
    const float* wq   = (const float*)d_in[3];   // query_weight
    const float* wv   = (const float*)d_in[4];   // value_weight
    float* out = (float*)d_out;

    cudaFuncSetAttribute(proj_kernel,
                         cudaFuncAttributeMaxDynamicSharedMemorySize, PROJ_SMEM);
    const int attn_smem = 98304 + 2048 + 128 + 128;   // 100608 B
    cudaFuncSetAttribute(attn_kernel,
                         cudaFuncAttributeMaxDynamicSharedMemorySize, attn_smem);

    proj_kernel<<<BB * SS / 32, 128, PROJ_SMEM>>>(x, wq, wk, wv);
    attn_kernel<<<BB * 64, 256, attn_smem>>>(mask, out);
}

// round 17
// speedup vs baseline: 5.1134x; 5.1134x over previous
#include <cuda_runtime.h>
#include <cstdint>

#define BB 8
#define SS 2048
#define DD 768
#define HH 12
#define LISTN 8

typedef unsigned long long ull;

// scratch (allocation-free rule: __device__ globals)
__device__ float g_q[BB * SS * HH];
__device__ float g_k[BB * SS * HH];
__device__ float g_v[BB * SS * HH];

// ---------- f32x2 helpers ----------
static __device__ __forceinline__ ull pk2(float a, float b) {
    ull r;
    asm("mov.b64 %0, {%1, %2};"
        : "=l"(r) : "r"(__float_as_uint(a)), "r"(__float_as_uint(b)));
    return r;
}
static __device__ __forceinline__ void upk2(ull v, float& a, float& b) {
    unsigned int x, y;
    asm("mov.b64 {%0, %1}, %2;" : "=r"(x), "=r"(y) : "l"(v));
    a = __uint_as_float(x);
    b = __uint_as_float(y);
}
static __device__ __forceinline__ void fma2(ull& d, ull a, ull b) {
    asm("fma.rn.f32x2 %0, %1, %2, %0;" : "+l"(d) : "l"(a), "l"(b));
}
static __device__ __forceinline__ ull add2(ull a, ull b) {
    ull r;
    asm("add.rn.f32x2 %0, %1, %2;" : "=l"(r) : "l"(a), "l"(b));
    return r;
}

// ---------- cp.async helpers ----------
static __device__ __forceinline__ void cpa16(void* smem, const void* g) {
    unsigned int sa = (unsigned int)__cvta_generic_to_shared(smem);
    asm volatile("cp.async.cg.shared.global [%0], [%1], 16;" :: "r"(sa), "l"(g));
}
static __device__ __forceinline__ void cpa_commit() {
    asm volatile("cp.async.commit_group;");
}
static __device__ __forceinline__ void cpa_wait1() {
    asm volatile("cp.async.wait_group 1;");
}
static __device__ __forceinline__ void cpa_wait0() {
    asm volatile("cp.async.wait_group 0;");
}

// =====================================================================
// Kernel 1: fused QKV projection — byte-exact R14 config (46.8us
// measured). 3-stage cp.async ring, ONE barrier per chunk (at the
// barrier everyone finished chunk ch-1, so staging into (ch+2)%3 ==
// (ch-1)%3 is race-free). 2 rows/thread, 256 blocks x 256 threads;
// rp = tid>>3 owns rows 2rp,2rp+1; sub = tid&7 splits D 8-way.
// =====================================================================
#define XS_F 4352              // 64*68 floats per x buffer
#define WS_F 2304              // 64*36 floats per W buffer
#define PROJ_SMEM ((3 * (XS_F + WS_F)) * 4)   // 79872 B

__global__ __launch_bounds__(256) void proj_kernel(
    const float* __restrict__ x,
    const float* __restrict__ wq,
    const float* __restrict__ wk,
    const float* __restrict__ wv)
{
    extern __shared__ __align__(16) float psm[];
    float* xs = psm;                 // [3][64*68]
    float* ws = psm + 3 * XS_F;      // [3][64*36]

    const int tid = threadIdx.x;
    const int sub = tid & 7;
    const int rp  = tid >> 3;
    const size_t rowBase = (size_t)blockIdx.x * 64;

    const float* warr[3] = { wq, wk, wv };

    // stage chunk (dc = ch*64) into ring slot s
    auto stage = [&](int s, int dc) {
        float* xb = xs + s * XS_F;
        float* wb = ws + s * WS_F;
#pragma unroll
        for (int i = tid; i < 1024; i += 256) {
            int row = i >> 4, col = i & 15;
            cpa16(&xb[row * 68 + col * 4],
                  x + (rowBase + row) * DD + dc + col * 4);
        }
        for (int i = tid; i < 576; i += 256) {
            int a = i / 192, rem = i - a * 192;
            int c = rem / 3,  j = rem - c * 3;
            cpa16(&wb[c * 36 + a * 12 + j * 4],
                  warr[a] + (size_t)dc * HH + rem * 4);
        }
        cpa_commit();
    };

    ull accA[18], accB[18];
#pragma unroll
    for (int i = 0; i < 18; i++) { accA[i] = 0ULL; accB[i] = 0ULL; }

    stage(0, 0);
    stage(1, 64);

    for (int ch = 0; ch < 12; ch++) {
        if (ch < 11) cpa_wait1();    // group ch complete (ch+1 may run)
        else         cpa_wait0();
        __syncthreads();             // chunk ch visible; everyone done ch-1
        if (ch < 10) stage((ch + 2) % 3, (ch + 2) * 64);

        const float* xb = xs + (ch % 3) * XS_F;
        const float* wb = ws + (ch % 3) * WS_F;
        const float* xrA = xb + (2 * rp) * 68;
        const float* xrB = xrA + 68;
#pragma unroll
        for (int ci = 0; ci < 8; ci++) {
            int c = ci * 8 + sub;
            ull xA = pk2(xrA[c], xrA[c]);
            ull xB = pk2(xrB[c], xrB[c]);
            const ulonglong2* wrow = (const ulonglong2*)(wb + c * 36);
#pragma unroll
            for (int j = 0; j < 9; j++) {
                ulonglong2 u = wrow[j];
                fma2(accA[2 * j],     xA, u.x);
                fma2(accA[2 * j + 1], xA, u.y);
                fma2(accB[2 * j],     xB, u.x);
                fma2(accB[2 * j + 1], xB, u.y);
            }
        }
    }

    // combine the 8 d-split partials (lanes sub 0..7 adjacent)
#pragma unroll
    for (int off = 1; off < 8; off <<= 1) {
#pragma unroll
        for (int j = 0; j < 18; j++) {
            accA[j] = add2(accA[j], __shfl_xor_sync(0xffffffffu, accA[j], off));
            accB[j] = add2(accB[j], __shfl_xor_sync(0xffffffffu, accB[j], off));
        }
    }

    if (sub == 0) {
#pragma unroll
        for (int half = 0; half < 2; half++) {
            ull* acc = half ? accB : accA;
            float o[36];
#pragma unroll
            for (int j = 0; j < 18; j++) upk2(acc[j], o[2 * j], o[2 * j + 1]);
            const size_t row = rowBase + 2 * rp + half;
            float4* qo = (float4*)&g_q[row * HH];
            float4* ko = (float4*)&g_k[row * HH];
            float4* vo = (float4*)&g_v[row * HH];
            qo[0] = make_float4(o[0],  o[1],  o[2],  o[3]);
            qo[1] = make_float4(o[4],  o[5],  o[6],  o[7]);
            qo[2] = make_float4(o[8],  o[9],  o[10], o[11]);
            ko[0] = make_float4(o[12], o[13], o[14], o[15]);
            ko[1] = make_float4(o[16], o[17], o[18], o[19]);
            ko[2] = make_float4(o[20], o[21], o[22], o[23]);
            vo[0] = make_float4(o[24], o[25], o[26], o[27]);
            vo[1] = make_float4(o[28], o[29], o[30], o[31]);
            vo[2] = make_float4(o[32], o[33], o[34], o[35]);
        }
    }
}

// =====================================================================
// Kernel 2: attention — byte-exact R11 config (51.7/51.4us measured).
// 256 blocks = (b, 64-row tile). 256 threads: quad = tid>>4 owns rows
// quad*4..+3; sub = tid&15 owns keys t==sub mod 16. K staged per
// 1024-key tile as duplicated pairs so FFMA2 needs no packing. Masked
// keys zeroed at staging. Register-only top-3 scores / top-2 indices
// per row; candidates to per-row shared lists; one gatherer per row.
// Overflow/empty -> exact per-row rescan recomputing the row max.
// =====================================================================
static __device__ __forceinline__ ull packSI(float s, int i) {
    return ((ull)__float_as_uint(s) << 32) | (unsigned int)i;
}

__global__ __launch_bounds__(256, 2) void attn_kernel(
    const int* __restrict__ mask,
    float* __restrict__ outp)
{
    extern __shared__ char smem_raw[];
    ulonglong2* ks = (ulonglong2*)smem_raw;              // 6144 * 16B = 98304
    ull*  slist = (ull*)(smem_raw + 98304);              // 64*8*8 = 4096
    int*  scnt  = (int*)(smem_raw + 98304 + 4096);       // 256
    int*  sflag = (int*)(smem_raw + 98304 + 4096 + 256); // 256

    const int tid  = threadIdx.x;
    const int b    = blockIdx.x >> 5;
    const int tile = blockIdx.x & 31;
    const int sub  = tid & 15;
    const int quad = tid >> 4;

    const float* kbase = g_k + (size_t)b * SS * HH;
    const float* vbase = g_v + (size_t)b * SS * HH;
    const int*   mb    = mask + b * SS;

    const float sc = 0.28867513459481287f;   // 1/sqrt(12)
    const size_t rowG0 = (size_t)b * SS + tile * 64 + quad * 4;

    if (tid < 64) { scnt[tid] = 0; sflag[tid] = 0; }

    // load 4 query rows, fold in scale, pack pairs (row0,row1)/(row2,row3)
    ull q01[12], q23[12];
    {
        const float4* qA = (const float4*)(g_q + rowG0 * HH);
        float4 r0a = qA[0], r0b = qA[1],  r0c = qA[2];
        float4 r1a = qA[3], r1b = qA[4],  r1c = qA[5];
        float4 r2a = qA[6], r2b = qA[7],  r2c = qA[8];
        float4 r3a = qA[9], r3b = qA[10], r3c = qA[11];
        q01[0]  = pk2(r0a.x*sc, r1a.x*sc);  q01[1]  = pk2(r0a.y*sc, r1a.y*sc);
        q01[2]  = pk2(r0a.z*sc, r1a.z*sc);  q01[3]  = pk2(r0a.w*sc, r1a.w*sc);
        q01[4]  = pk2(r0b.x*sc, r1b.x*sc);  q01[5]  = pk2(r0b.y*sc, r1b.y*sc);
        q01[6]  = pk2(r0b.z*sc, r1b.z*sc);  q01[7]  = pk2(r0b.w*sc, r1b.w*sc);
        q01[8]  = pk2(r0c.x*sc, r1c.x*sc);  q01[9]  = pk2(r0c.y*sc, r1c.y*sc);
        q01[10] = pk2(r0c.z*sc, r1c.z*sc);  q01[11] = pk2(r0c.w*sc, r1c.w*sc);
        q23[0]  = pk2(r2a.x*sc, r3a.x*sc);  q23[1]  = pk2(r2a.y*sc, r3a.y*sc);
        q23[2]  = pk2(r2a.z*sc, r3a.z*sc);  q23[3]  = pk2(r2a.w*sc, r3a.w*sc);
        q23[4]  = pk2(r2b.x*sc, r3b.x*sc);  q23[5]  = pk2(r2b.y*sc, r3b.y*sc);
        q23[6]  = pk2(r2b.z*sc, r3b.z*sc);  q23[7]  = pk2(r2b.w*sc, r3b.w*sc);
        q23[8]  = pk2(r2c.x*sc, r3c.x*sc);  q23[9]  = pk2(r2c.y*sc, r3c.y*sc);
        q23[10] = pk2(r2c.z*sc, r3c.z*sc);  q23[11] = pk2(r2c.w*sc, r3c.w*sc);
    }

    const float NINF = __int_as_float(0xff800000);
    float t1[4], t2[4], t3[4], th[4];
    int   j1[4], j2[4];
#pragma unroll
    for (int r = 0; r < 4; r++) {
        t1[r] = NINF; t2[r] = NINF; t3[r] = NINF;
        th[r] = 0.f;                 // floor 0: masked-zero keys never enter
        j1[r] = 0; j2[r] = 0;
    }

    // ---------- pass 1: two 1024-key tiles ----------
    for (int kt = 0; kt < 2; kt++) {
        __syncthreads();
        // stage duplicated key pairs, zero masked keys
        for (int tt = tid; tt < 1024; tt += 256) {
            int gk = (kt << 10) + tt;
            const float4* kr = (const float4*)(kbase + (size_t)gk * HH);
            float4 w0 = kr[0], w1 = kr[1], w2 = kr[2];
            if (!mb[gk]) { w0 = make_float4(0,0,0,0); w1 = w0; w2 = w0; }
            ulonglong2 u;
            u.x = pk2(w0.x, w0.x); u.y = pk2(w0.y, w0.y); ks[0*1024 + tt] = u;
            u.x = pk2(w0.z, w0.z); u.y = pk2(w0.w, w0.w); ks[1*1024 + tt] = u;
            u.x = pk2(w1.x, w1.x); u.y = pk2(w1.y, w1.y); ks[2*1024 + tt] = u;
            u.x = pk2(w1.z, w1.z); u.y = pk2(w1.w, w1.w); ks[3*1024 + tt] = u;
            u.x = pk2(w2.x, w2.x); u.y = pk2(w2.y, w2.y); ks[4*1024 + tt] = u;
            u.x = pk2(w2.z, w2.z); u.y = pk2(w2.w, w2.w); ks[5*1024 + tt] = u;
        }
        __syncthreads();

        for (int it = 0; it < 64; it++) {
            int t = (it << 4) + sub;
            ull a0 = 0ULL, a1 = 0ULL;
#pragma unroll
            for (int j = 0; j < 6; j++) {
                ulonglong2 u = ks[j * 1024 + t];
                fma2(a0, q01[2 * j],     u.x);
                fma2(a0, q01[2 * j + 1], u.y);
                fma2(a1, q23[2 * j],     u.x);
                fma2(a1, q23[2 * j + 1], u.y);
            }
            float sv[4];
            upk2(a0, sv[0], sv[1]);
            upk2(a1, sv[2], sv[3]);
            int g = (kt << 10) + t;
#pragma unroll
            for (int r = 0; r < 4; r++) {
                float s = sv[r];
                if (s > th[r]) {                       // rare
                    if (s > t1[r]) {
                        t3[r] = t2[r];
                        t2[r] = t1[r]; j2[r] = j1[r];
                        t1[r] = s;     j1[r] = g;
                        th[r] = fmaxf(s - 30.f, 0.f);
                    } else if (s > t2[r]) {
                        t3[r] = t2[r];
                        t2[r] = s; j2[r] = g;
                    } else {
                        t3[r] = fmaxf(t3[r], s);
                    }
                }
            }
        }
    }

    // row maxes across the 16 sub-threads
    float mrow[4];
#pragma unroll
    for (int r = 0; r < 4; r++) mrow[r] = t1[r];
#pragma unroll
    for (int off = 1; off < 16; off <<= 1) {
#pragma unroll
        for (int r = 0; r < 4; r++)
            mrow[r] = fmaxf(mrow[r], __shfl_xor_sync(0xffffffffu, mrow[r], off));
    }

    // publish candidates to per-row lists
#pragma unroll
    for (int r = 0; r < 4; r++) {
        int row = (quad << 2) + r;
        float thr = mrow[r] - 30.f;
        if (t1[r] > thr) {
            int slot = atomicAdd(&scnt[row], 1);
            if (slot < LISTN) slist[row * LISTN + slot] = packSI(t1[r], j1[r]);
        }
        if (t2[r] > thr) {
            int slot = atomicAdd(&scnt[row], 1);
            if (slot < LISTN) slist[row * LISTN + slot] = packSI(t2[r], j2[r]);
        }
        if (t3[r] > thr) sflag[row] = 1;
    }
    __syncthreads();

    // ---------- pass 2: gather (one thread per row; sub==0 does its 4 rows)
    if (sub == 0) {
#pragma unroll
        for (int r = 0; r < 4; r++) {
            int row = (quad << 2) + r;
            float den = 0.f;
            float o[12];
#pragma unroll
            for (int h = 0; h < 12; h++) o[h] = 0.f;

            int n = scnt[row];
            if (n > 0 && n <= LISTN && !sflag[row]) {
                float m = mrow[r];
                for (int e = 0; e < n; e++) {
                    ull v = slist[row * LISTN + e];
                    float s = __uint_as_float((unsigned int)(v >> 32));
                    int idx = (int)(v & 0xffffffffu);
                    float pe = __expf(s - m);
                    den += pe;
                    const float4* vr = (const float4*)(vbase + (size_t)idx * HH);
                    float4 v0 = vr[0], v1 = vr[1], v2 = vr[2];
                    o[0] += pe * v0.x;  o[1] += pe * v0.y;  o[2] += pe * v0.z;  o[3] += pe * v0.w;
                    o[4] += pe * v1.x;  o[5] += pe * v1.y;  o[6] += pe * v1.z;  o[7] += pe * v1.w;
                    o[8] += pe * v2.x;  o[9] += pe * v2.y;  o[10]+= pe * v2.z;  o[11]+= pe * v2.w;
                }
            } else {
                // exact fallback: two sweeps over the whole row from global,
                // recomputing the true row max (independent of pass-1 state)
                float qs[12];
                const float4* qp = (const float4*)(g_q + (rowG0 + r) * HH);
                float4 a = qp[0], b4 = qp[1], c4 = qp[2];
                qs[0] = a.x * sc;  qs[1] = a.y * sc;  qs[2] = a.z * sc;  qs[3] = a.w * sc;
                qs[4] = b4.x * sc; qs[5] = b4.y * sc; qs[6] = b4.z * sc; qs[7] = b4.w * sc;
                qs[8] = c4.x * sc; qs[9] = c4.y * sc; qs[10]= c4.z * sc; qs[11]= c4.w * sc;

                float m = NINF;
                for (int ti = 0; ti < SS; ti++) {
                    if (mb[ti]) {
                        const float4* kr = (const float4*)(kbase + (size_t)ti * HH);
                        float4 k0 = kr[0], k1 = kr[1], k2 = kr[2];
                        float s = qs[0]*k0.x + qs[1]*k0.y + qs[2]*k0.z + qs[3]*k0.w
                                + qs[4]*k1.x + qs[5]*k1.y + qs[6]*k1.z + qs[7]*k1.w
                                + qs[8]*k2.x + qs[9]*k2.y + qs[10]*k2.z + qs[11]*k2.w;
                        m = fmaxf(m, s);
                    }
                }
                for (int ti = 0; ti < SS; ti++) {
                    if (mb[ti]) {
                        const float4* kr = (const float4*)(kbase + (size_t)ti * HH);
                        float4 k0 = kr[0], k1 = kr[1], k2 = kr[2];
                        float s = qs[0]*k0.x + qs[1]*k0.y + qs[2]*k0.z + qs[3]*k0.w
                                + qs[4]*k1.x + qs[5]*k1.y + qs[6]*k1.z + qs[7]*k1.w
                                + qs[8]*k2.x + qs[9]*k2.y + qs[10]*k2.z + qs[11]*k2.w;
                        if (s > m - 40.f) {
                            float pe = __expf(s - m);
                            den += pe;
                            const float4* vr = (const float4*)(vbase + (size_t)ti * HH);
                            float4 v0 = vr[0], v1 = vr[1], v2 = vr[2];
                            o[0] += pe * v0.x;  o[1] += pe * v0.y;  o[2] += pe * v0.z;  o[3] += pe * v0.w;
                            o[4] += pe * v1.x;  o[5] += pe * v1.y;  o[6] += pe * v1.z;  o[7] += pe * v1.w;
                            o[8] += pe * v2.x;  o[9] += pe * v2.y;  o[10]+= pe * v2.z;  o[11]+= pe * v2.w;
                        }
                    }
                }
            }

            float inv = 1.f / den;
            float4* op = (float4*)(outp + (rowG0 + r) * HH);
            op[0] = make_float4(o[0]*inv, o[1]*inv, o[2]*inv,  o[3]*inv);
            op[1] = make_float4(o[4]*inv, o[5]*inv, o[6]*inv,  o[7]*inv);
            op[2] = make_float4(o[8]*inv, o[9]*inv, o[10]*inv, o[11]*inv);
        }
    }
}

// =====================================================================
// launch
// =====================================================================
extern "C" void kernel_launch(void* const* d_in, const int* in_sizes, int n_in,
                              void* d_out, int out_size) {
    const float* x    = (const float*)d_in[0];
    const int*   mask = (const int*)d_in[1];
    const float* wk   = (const float*)d_in[2];   // key_weight
    const float* wq   = (const float*)d_in[3];   // query_weight
    const float* wv   = (const float*)d_in[4];   // value_weight
    float* out = (float*)d_out;

    cudaFuncSetAttribute(proj_kernel,
                         cudaFuncAttributeMaxDynamicSharedMemorySize, PROJ_SMEM);
    const int attn_smem = 98304 + 4096 + 256 + 256;   // 102912 B
    cudaFuncSetAttribute(attn_kernel,
                         cudaFuncAttributeMaxDynamicSharedMemorySize, attn_smem);

    proj_kernel<<<BB * SS / 64, 256, PROJ_SMEM>>>(x, wq, wk, wv);
    attn_kernel<<<BB * 32, 256, attn_smem>>>(mask, out);
}